// round 15
// baseline (speedup 1.0000x reference)
#include <cuda_runtime.h>
#include <math.h>
#include <stdint.h>

#define NQ    12
#define TT    8
#define BB    32
#define SHOTS 256
#define KMAX  80
#define DIM   4096
#define NTHR  1024

typedef unsigned long long u64;

// Evolved states exp(-i t H)|init>, one complex vector per t, plus sync flags.
__device__ float2 g_states[TT][DIM];
__device__ int    g_flag[TT];   // counts ranks published (0..2); self-cleaning
__device__ int    g_cnt[TT];    // consumer count for self-clean (16 per t)

__device__ __forceinline__ int ld_acquire(const int* p) {
    int v;
    asm volatile("ld.acquire.gpu.s32 %0, [%1];" : "=r"(v) : "l"(p) : "memory");
    return v;
}
__device__ __forceinline__ uint32_t smem_u32(const void* p) {
    uint32_t a;
    asm("{ .reg .u64 t; cvta.to.shared.u64 t, %1; cvt.u32.u64 %0, t; }"
        : "=r"(a) : "l"(p));
    return a;
}
__device__ __forceinline__ uint32_t mapa32(uint32_t a, uint32_t r) {
    uint32_t d;
    asm("mapa.shared::cluster.u32 %0, %1, %2;" : "=r"(d) : "r"(a), "r"(r));
    return d;
}
__device__ __forceinline__ void mbar_wait(uint32_t bar, uint32_t parity) {
    asm volatile(
        "{\n\t.reg .pred P;\n\t"
        "WL_%=:\n\t"
        "mbarrier.try_wait.parity.acquire.cta.shared::cta.b64 P, [%0], %1, 0x989680;\n\t"
        "@P bra.uni WD_%=;\n\t"
        "bra.uni WL_%=;\n\t"
        "WD_%=:\n\t}"
        :: "r"(bar), "r"(parity) : "memory");
}
__device__ __forceinline__ void mbar_expect(uint32_t bar, uint32_t bytes) {
    asm volatile("mbarrier.arrive.expect_tx.shared.b64 _, [%0], %1;"
                 :: "r"(bar), "r"(bytes) : "memory");
}
__device__ __forceinline__ void bulk_s2s(uint32_t dst, uint32_t src,
                                         uint32_t bytes, uint32_t rbar) {
    asm volatile(
        "cp.async.bulk.shared::cluster.shared::cta.mbarrier::complete_tx::bytes "
        "[%0], [%1], %2, [%3];"
        :: "r"(dst), "r"(src), "r"(bytes), "r"(rbar) : "memory");
}

// ---------------------------------------------------------------------------
// One Chebyshev term on a CTA half (2048 entries), 1024 threads, 2 floats
// per thread packed in one float2 slot: local s = (tid<<1)|c, global adds
// rank<<11. Taps: bit0 = in-slot swap (regs); bits1..10 = 10 smem LDS.64;
// bit11 = peer mirror LDS.64 (after tx-barrier wait). Protocol = R9/R11.
// Scalar FMA throughout to stay under the 64-reg/thread cap at 1024 thr.
// ---------------------------------------------------------------------------
template<bool EVEN>
__device__ __forceinline__ void cheb_term(
    float& c0, float& c1, float& p0, float& p1,
    float& pr0, float& pr1, float& pi0, float& pi1,
    float d0, float d1, const float (&px)[12],
    const float2* __restrict__ SRC, float2* __restrict__ DST,
    const float2* __restrict__ MIR,
    uint32_t bar_in, int& ph_in, bool do_wait,
    uint32_t bulk_dst, uint32_t bulk_src, uint32_t bulk_rbar, bool do_send,
    const int (&tapx)[10], int tid, float coef)
{
    float a0 = d0 * c0;
    float a1 = d1 * c1;
    a0 = fmaf(px[0], c1, a0);            // bit 0: swap within slot
    a1 = fmaf(px[0], c0, a1);
    // bits 1..10: own-half smem taps (conflict-free LDS.64)
#pragma unroll
    for (int b = 0; b < 10; b++) {
        const float2 v = SRC[tapx[b]];
        a0 = fmaf(px[1 + b], v.x, a0);
        a1 = fmaf(px[1 + b], v.y, a1);
    }
    // wait for peer mirror (sent last term; usually complete), re-post expect
    if (do_wait) {
        mbar_wait(bar_in, (uint32_t)ph_in);
        ph_in ^= 1;
        if (tid == 0) mbar_expect(bar_in, 8192u);
    }
    // bit 11: peer mirror (ordered after the acquire wait above)
    {
        const float2 m = MIR[tid];
        a0 = fmaf(px[11], m.x, a0);
        a1 = fmaf(px[11], m.y, a1);
    }
    const float n0 = fmaf(2.f, a0, -p0);   // 2*acc - prev
    const float n1 = fmaf(2.f, a1, -p1);
    DST[tid] = make_float2(n0, n1);
    p0 = c0; p1 = c1;
    c0 = n0; c1 = n1;
    if (EVEN) { pr0 = fmaf(coef, n0, pr0); pr1 = fmaf(coef, n1, pr1); }
    else      { pi0 = fmaf(coef, n0, pi0); pi1 = fmaf(coef, n1, pi1); }

    __syncthreads();   // all stores of this generation visible CTA-wide

    if (do_send && tid == 0) {
        asm volatile("fence.proxy.async.shared::cta;" ::: "memory");
        bulk_s2s(bulk_dst, bulk_src, 8192u, bulk_rbar);
    }
}

// ---------------------------------------------------------------------------
// radix-2 gate on a complex pair (X basis p=0, Y basis p=1), no scaling
// ---------------------------------------------------------------------------
__device__ __forceinline__ void gate2(int p, float& r0, float& i0,
                                      float& r1, float& i1)
{
    const float a = r0, bb = i0, c = r1, d = i1;
    if (p == 0) { r0 = a + c; i0 = bb + d; r1 = a - c; i1 = bb - d; }
    else        { r0 = a + d; i0 = bb - c; r1 = a - d; i1 = bb + c; }
}

// ---------------------------------------------------------------------------
// Fused persistent kernel. 128 CTAs x 1024 threads, cluster size 2.
//   bid 0..15 : evolve t=bid>>1, rank=bid&1 (2-CTA cluster per t).
//   ALL CTAs  : then measure t = bid>>4, tasks b = 2*(bid&15), +1.
// Single wave (128 CTAs <= 148 SMs at 1 CTA/SM), so flag spinning is safe.
// ---------------------------------------------------------------------------
__global__ void __cluster_dims__(2, 1, 1) __launch_bounds__(NTHR, 1)
fused_kernel(const int* __restrict__ d_init,
             const float* __restrict__ d_ts,
             const int* __restrict__ d_pauli,
             const int* __restrict__ d_idx,
             const float* __restrict__ d_px,
             const float* __restrict__ d_pzz,
             float* __restrict__ d_out)
{
    // pool (32KB): buf0|buf1|mir0|mir1 (8KB each = 1024 float2); coeffs after.
    // measure reuses [0, DIM) = re, [DIM, 2*DIM) = im.
    __shared__ __align__(16) float pool[2 * DIM + 2 * (KMAX + 1)];
    __shared__ __align__(8) unsigned long long s_bar[2];
    __shared__ int s_misc[3 * NQ + 2];

    const int tid = threadIdx.x;
    const int bid = blockIdx.x;

    if (bid < 2 * TT) {
        // ================= EVOLVE (t = bid>>1, rank = bid&1) ================
        const int t = bid >> 1;
        float2* slots = reinterpret_cast<float2*>(pool);
        float2* buf0 = slots;            // gen-even
        float2* buf1 = slots + 1024;     // gen-odd
        float2* mir0 = slots + 2048;     // peer gen-even
        float2* mir1 = slots + 3072;     // peer gen-odd
        float* s_cr = pool + 2 * DIM;
        float* s_ci = s_cr + (KMAX + 1);

        uint32_t rank;
        asm("mov.u32 %0, %%cluster_ctarank;" : "=r"(rank));
        const uint32_t peer = rank ^ 1u;

        float px[12];
        float lambda = 0.f;
#pragma unroll
        for (int i = 0; i < NQ; i++) { px[i] = d_px[i]; lambda += fabsf(px[i]); }
        float pzz[NQ - 1];
#pragma unroll
        for (int i = 0; i < NQ - 1; i++) { pzz[i] = d_pzz[i]; lambda += fabsf(pzz[i]); }
        if (lambda < 1e-20f) lambda = 1e-20f;
        const float inv_l = 1.0f / lambda;
#pragma unroll
        for (int i = 0; i < NQ; i++) px[i] *= inv_l;

        // scaled diagonal for owned entries: s = (rank<<11)|(tid<<1)|c
        float diag[2];
#pragma unroll
        for (int c = 0; c < 2; c++) {
            const int s = ((int)rank << 11) | (tid << 1) | c;
            float d = 0.f;
#pragma unroll
            for (int i = 0; i < NQ - 1; i++) {
                const int bi = (s >> i) & 1;
                const int bj = (s >> (i + 1)) & 1;
                d += (bi == bj) ? pzz[i] : -pzz[i];
            }
            diag[c] = d * inv_l;
        }

        // thread 0: Bessel coefficients + adaptive trim + barrier init
        if (tid == 0) {
            double x = (double)d_ts[t] * (double)lambda;
            if (x < 1e-5) x = 1e-5;
            int K = (int)ceil(x) + 16;
            if (K > KMAX) K = KMAX;
            if (K < 2)    K = 2;
            const int M = K + 14;
            double v[KMAX + 16];
            v[M] = 1e-30;
            const double inv_x = 1.0 / x;
            double up = 0.0;
            for (int k = M; k >= 1; k--) {
                const double nv = (2.0 * (double)k * inv_x) * v[k] - up;
                up = v[k];
                v[k - 1] = nv;
            }
            double S = v[0];
            for (int m = 2; m <= M; m += 2) S += 2.0 * v[m];
            const double invS = 1.0 / S;
            while (K > 2 && fabs(v[K] * invS) < 4e-4) K--;   // adaptive trim
            for (int k = 0; k <= K; k++) {
                const double Jk = v[k] * invS;
                const double c  = (k == 0) ? Jk : 2.0 * Jk;
                float cr = 0.f, ci = 0.f;
                switch (k & 3) {         // (-i)^k
                    case 0: cr = (float)c;  break;
                    case 1: ci = (float)-c; break;
                    case 2: cr = (float)-c; break;
                    case 3: ci = (float)c;  break;
                }
                s_cr[k] = cr;
                s_ci[k] = ci;
            }
            s_misc[0] = K;
            const uint32_t b0 = smem_u32(&s_bar[0]);
            const uint32_t b1 = smem_u32(&s_bar[1]);
            asm volatile("mbarrier.init.shared.b64 [%0], 1;" :: "r"(b0) : "memory");
            asm volatile("mbarrier.init.shared.b64 [%0], 1;" :: "r"(b1) : "memory");
            mbar_expect(b0, 8192u);      // phase 0, stage 0 (even gens)
            mbar_expect(b1, 8192u);      // phase 0, stage 1 (odd gens)
        }
        __syncthreads();

        const int K    = s_misc[0];
        const int init = *d_init;

        // tap slot-indices and remote addresses
        int tapx[10];
#pragma unroll
        for (int b2 = 0; b2 < 10; b2++) tapx[b2] = tid ^ (1 << b2);
        const uint32_t pbase = smem_u32(pool);
        const uint32_t bar0 = smem_u32(&s_bar[0]);
        const uint32_t bar1 = smem_u32(&s_bar[1]);
        const uint32_t pmir0 = mapa32(pbase + 16384u, peer);
        const uint32_t pmir1 = mapa32(pbase + 24576u, peer);
        const uint32_t pbar0 = mapa32(bar0, peer);
        const uint32_t pbar1 = mapa32(bar1, peer);

        // phi_0 = e_init ; phi_1 = H' e_init (analytic), own half + peer mirror
        float c0, c1, p0, p1, pr0, pr1, pi0, pi1;
        {
            const float cr0 = s_cr[0], ci1 = s_ci[1];
            float p0v[2], p1v[2], q1v[2];
#pragma unroll
            for (int c = 0; c < 2; c++) {
                const int so = ((int)rank << 11) | (tid << 1) | c;
                const int sp = ((int)peer << 11) | (tid << 1) | c;
                p0v[c] = (so == init) ? 1.f : 0.f;
                float pv = (so == init) ? diag[c] : 0.f;
                int d = so ^ init;
#pragma unroll
                for (int i = 0; i < NQ; i++)
                    if (d == (1 << i)) pv = px[i];
                p1v[c] = pv;
                float q1 = 0.f;
                if (sp == init) {
                    float dd = 0.f;
#pragma unroll
                    for (int i = 0; i < NQ - 1; i++) {
                        const int bi = (sp >> i) & 1, bj = (sp >> (i + 1)) & 1;
                        dd += (bi == bj) ? pzz[i] : -pzz[i];
                    }
                    q1 = dd * inv_l;
                }
                d = sp ^ init;
#pragma unroll
                for (int i = 0; i < NQ; i++)
                    if (d == (1 << i)) q1 = px[i];
                q1v[c] = q1;
            }
            c0 = p1v[0]; c1 = p1v[1];
            p0 = p0v[0]; p1 = p0v[1];
            pr0 = cr0 * p0v[0]; pr1 = cr0 * p0v[1];
            pi0 = ci1 * p1v[0]; pi1 = ci1 * p1v[1];
            buf1[tid] = make_float2(c0, c1);          // phi_1 (odd gen)
            mir1[tid] = make_float2(q1v[0], q1v[1]);  // peer phi_1 (analytic)
        }
        __syncthreads();
        asm volatile("barrier.cluster.arrive.aligned;" ::: "memory");
        asm volatile("barrier.cluster.wait.aligned;"   ::: "memory");

        int ph0 = 0, ph1 = 0;
        for (int k = 2; k <= K; k += 2) {
            // even k: consumes buf1/mir1 (gen k-1), produces buf0, sends buf0
            cheb_term<true>(c0, c1, p0, p1, pr0, pr1, pi0, pi1,
                            diag[0], diag[1], px,
                            buf1, buf0, mir1,
                            bar1, ph1, (k > 2),
                            pmir0, pbase, pbar0, (k < K),
                            tapx, tid, s_cr[k]);
            if (k + 1 <= K)
                cheb_term<false>(c0, c1, p0, p1, pr0, pr1, pi0, pi1,
                                 diag[0], diag[1], px,
                                 buf0, buf1, mir0,
                                 bar0, ph0, true,
                                 pmir1, pbase + 8192u, pbar1, (k + 1 < K),
                                 tapx, tid, s_ci[k + 1]);
        }

        // publish my half + count flag
        {
            const int s = ((int)rank << 11) | (tid << 1);
            g_states[t][s]     = make_float2(pr0, pi0);
            g_states[t][s | 1] = make_float2(pr1, pi1);
        }
        __syncthreads();
        if (tid == 0) {
            __threadfence();
            atomicAdd(&g_flag[t], 1);
        }
        // keep cluster alive until both ranks stop touching peer smem
        asm volatile("barrier.cluster.arrive.aligned;" ::: "memory");
        asm volatile("barrier.cluster.wait.aligned;"   ::: "memory");
    }

    // ================= WAIT for both halves of measure-t =================
    const int t  = bid >> 4;
    const int bp = bid & 15;
    if (tid == 0) {
        while (ld_acquire(&g_flag[t]) < 2) __nanosleep(64);
        const int n = atomicAdd(&g_cnt[t], 1);
        if (n == 15) {               // last of 16 consumer CTAs: self-clean
            g_cnt[t]  = 0;
            g_flag[t] = 0;
        }
    }
    __syncthreads();

    // ================= MEASURE: two tasks (t, 2*bp) and (t, 2*bp+1) ========
    for (int task = 0; task < 2; task++) {
        const int b = 2 * bp + task;
        float* re = pool;
        float* im = pool + DIM;
        int* p_raw = s_misc;
        int* nzm   = s_misc + NQ;
        int* nzp   = s_misc + 2 * NQ;
        int* s_nnz = s_misc + 3 * NQ;

        if (tid < NQ) p_raw[tid] = d_pauli[b * NQ + tid];

#pragma unroll
        for (int r = 0; r < DIM / NTHR; r++) {
            const int s = tid + (r << 10);
            const float2 v = __ldcg(&g_states[t][s]);
            re[s] = v.x;
            im[s] = v.y;
        }
        __syncthreads();

        if (tid == 0) {
            int c = 0;
            for (int m = NQ - 1; m >= 0; m--) {
                const int p = p_raw[NQ - 1 - m];
                if (p != 2) { nzm[c] = m; nzp[c] = p; c++; }
            }
            *s_nnz = c;
        }
        __syncthreads();

        const int nnz = *s_nnz;
        int i = 0;
        // radix-8: three non-Z qubits per sweep (mh > mm > ml); 512 groups
        for (; i + 2 < nnz; i += 3) {
            const int mh = nzm[i], mm = nzm[i + 1], ml = nzm[i + 2];
            const int ph_ = nzp[i], pm_ = nzp[i + 1], pl_ = nzp[i + 2];
            if (tid < 512) {
                const int lml = (1 << ml) - 1;
                const int lmm = (1 << mm) - 1;
                const int lmh = (1 << mh) - 1;
                const int ol = 1 << ml, om = 1 << mm, oh = 1 << mh;
                int x = ((tid & ~lml) << 1) | (tid & lml);
                x = ((x & ~lmm) << 1) | (x & lmm);
                const int s0 = ((x & ~lmh) << 1) | (x & lmh);
                int sidx[8];
#pragma unroll
                for (int j = 0; j < 8; j++)
                    sidx[j] = s0 | ((j & 1) ? ol : 0) | ((j & 2) ? om : 0) | ((j & 4) ? oh : 0);
                float rr[8], ii[8];
#pragma unroll
                for (int j = 0; j < 8; j++) { rr[j] = re[sidx[j]]; ii[j] = im[sidx[j]]; }
#pragma unroll
                for (int j = 0; j < 8; j += 2)
                    gate2(pl_, rr[j], ii[j], rr[j + 1], ii[j + 1]);
#pragma unroll
                for (int j = 0; j < 2; j++) {
                    gate2(pm_, rr[j], ii[j], rr[j + 2], ii[j + 2]);
                    gate2(pm_, rr[j + 4], ii[j + 4], rr[j + 6], ii[j + 6]);
                }
#pragma unroll
                for (int j = 0; j < 4; j++)
                    gate2(ph_, rr[j], ii[j], rr[j + 4], ii[j + 4]);
                const float sc = 0.35355339059327376f;   // (1/sqrt2)^3
#pragma unroll
                for (int j = 0; j < 8; j++) {
                    re[sidx[j]] = rr[j] * sc;
                    im[sidx[j]] = ii[j] * sc;
                }
            }
            __syncthreads();
        }
        // leftover: two non-Z qubits (radix-4); 1024 groups
        if (i + 1 < nnz) {
            const int mh = nzm[i], ml = nzm[i + 1];
            const int ph_ = nzp[i], pl_ = nzp[i + 1];
            const int lml = (1 << ml) - 1;
            const int lmh = (1 << mh) - 1;
            const int ol = 1 << ml, oh = 1 << mh;
            const int x = ((tid & ~lml) << 1) | (tid & lml);
            const int s00 = ((x & ~lmh) << 1) | (x & lmh);
            float rr[4], ii[4];
            const int sidx[4] = { s00, s00 | ol, s00 | oh, s00 | oh | ol };
#pragma unroll
            for (int j = 0; j < 4; j++) { rr[j] = re[sidx[j]]; ii[j] = im[sidx[j]]; }
            gate2(pl_, rr[0], ii[0], rr[1], ii[1]);
            gate2(pl_, rr[2], ii[2], rr[3], ii[3]);
            gate2(ph_, rr[0], ii[0], rr[2], ii[2]);
            gate2(ph_, rr[1], ii[1], rr[3], ii[3]);
#pragma unroll
            for (int j = 0; j < 4; j++) {
                re[sidx[j]] = rr[j] * 0.5f;
                im[sidx[j]] = ii[j] * 0.5f;
            }
            i += 2;
            __syncthreads();
        }
        // leftover: single non-Z qubit (radix-2); 2048 pairs
        if (i < nnz) {
            const int m = nzm[i], p = nzp[i];
            const int lm = (1 << m) - 1;
            const float s2 = 0.70710678118654752f;
#pragma unroll
            for (int r = 0; r < 2; r++) {
                const int q  = tid + (r << 10);
                const int sA = ((q & ~lm) << 1) | (q & lm);
                const int sB = sA | (1 << m);
                float r0 = re[sA], i0 = im[sA];
                float r1 = re[sB], i1 = im[sB];
                gate2(p, r0, i0, r1, i1);
                re[sA] = r0 * s2; im[sA] = i0 * s2;
                re[sB] = r1 * s2; im[sB] = i1 * s2;
            }
            __syncthreads();
        }

        if (tid < SHOTS) {
            const int base2 = (t * BB + b) * SHOTS;
            const int idx   = d_idx[base2 + tid];
            const float pr  = re[idx];
            const float pi  = im[idx];
            d_out[base2 + tid] = pr * pr + pi * pi;
        }
        __syncthreads();   // before re/im reload for the next task
    }
}

// ---------------------------------------------------------------------------
extern "C" void kernel_launch(void* const* d_in, const int* in_sizes, int n_in,
                              void* d_out, int out_size)
{
    const int*   d_init  = (const int*)  d_in[0];
    const float* d_ts    = (const float*)d_in[1];
    const int*   d_pauli = (const int*)  d_in[2];
    const int*   d_idx   = (const int*)  d_in[3];
    const float* d_px    = (const float*)d_in[4];
    const float* d_pzz   = (const float*)d_in[5];

    fused_kernel<<<TT * BB / 2, NTHR>>>(d_init, d_ts, d_pauli, d_idx,
                                        d_px, d_pzz, (float*)d_out);
}

// round 16
// speedup vs baseline: 1.1918x; 1.1918x over previous
#include <cuda_runtime.h>
#include <math.h>
#include <stdint.h>

#define NQ    12
#define TT    8
#define BB    32
#define SHOTS 256
#define KMAX  80
#define DIM   4096

typedef unsigned long long u64;

// Evolved states exp(-i t H)|init>, one complex vector per t, plus sync flags.
__device__ float2 g_states[TT][DIM];
__device__ int    g_flag[TT];   // counts ranks published (0..2); self-cleaning
__device__ int    g_cnt[TT];    // consumer count for self-clean

__device__ __forceinline__ int ld_acquire(const int* p) {
    int v;
    asm volatile("ld.acquire.gpu.s32 %0, [%1];" : "=r"(v) : "l"(p) : "memory");
    return v;
}
__device__ __forceinline__ uint32_t smem_u32(const void* p) {
    uint32_t a;
    asm("{ .reg .u64 t; cvta.to.shared.u64 t, %1; cvt.u32.u64 %0, t; }"
        : "=r"(a) : "l"(p));
    return a;
}
__device__ __forceinline__ uint32_t mapa32(uint32_t a, uint32_t r) {
    uint32_t d;
    asm("mapa.shared::cluster.u32 %0, %1, %2;" : "=r"(d) : "r"(a), "r"(r));
    return d;
}
__device__ __forceinline__ void mbar_wait(uint32_t bar, uint32_t parity) {
    asm volatile(
        "{\n\t.reg .pred P;\n\t"
        "WL_%=:\n\t"
        "mbarrier.try_wait.parity.acquire.cta.shared::cta.b64 P, [%0], %1, 0x989680;\n\t"
        "@P bra.uni WD_%=;\n\t"
        "bra.uni WL_%=;\n\t"
        "WD_%=:\n\t}"
        :: "r"(bar), "r"(parity) : "memory");
}
__device__ __forceinline__ void mbar_expect(uint32_t bar, uint32_t bytes) {
    asm volatile("mbarrier.arrive.expect_tx.shared.b64 _, [%0], %1;"
                 :: "r"(bar), "r"(bytes) : "memory");
}
__device__ __forceinline__ void bulk_s2s(uint32_t dst, uint32_t src,
                                         uint32_t bytes, uint32_t rbar) {
    asm volatile(
        "cp.async.bulk.shared::cluster.shared::cta.mbarrier::complete_tx::bytes "
        "[%0], [%1], %2, [%3];"
        :: "r"(dst), "r"(src), "r"(bytes), "r"(rbar) : "memory");
}

// ---- packed f32x2 helpers ----
__device__ __forceinline__ u64 pk2(float lo, float hi) {
    u64 r; asm("mov.b64 %0, {%1,%2};" : "=l"(r) : "f"(lo), "f"(hi)); return r;
}
__device__ __forceinline__ void upk2(u64 v, float& lo, float& hi) {
    asm("mov.b64 {%0,%1}, %2;" : "=f"(lo), "=f"(hi) : "l"(v));
}
__device__ __forceinline__ u64 swap2(u64 v) {
    float lo, hi; upk2(v, lo, hi); return pk2(hi, lo);
}
__device__ __forceinline__ u64 fma2_(u64 a, u64 b, u64 c) {
    u64 d; asm("fma.rn.f32x2 %0, %1, %2, %3;" : "=l"(d) : "l"(a), "l"(b), "l"(c));
    return d;
}
__device__ __forceinline__ u64 mul2_(u64 a, u64 b) {
    u64 d; asm("mul.rn.f32x2 %0, %1, %2;" : "=l"(d) : "l"(a), "l"(b)); return d;
}

// ---------------------------------------------------------------------------
// Rigorous spectral bound, tighter than the 1-norm:
//   H = sum_i [ x_i X_i + (assigned ZZ bonds at site i) ]
// Each site term h_i = x_i X_i + D_i with D_i diagonal, every assigned bond
// containing Z_i -> {X_i, D_i} = 0 -> ||h_i|| = sqrt(x_i^2 + (sum |zz|)^2).
// lambda = min over bond->site assignments of sum_i ||h_i||  (2-state DP).
// ---------------------------------------------------------------------------
__device__ __forceinline__ float lambda_bound(const float (&px)[NQ],
                                              const float (&pzz)[NQ - 1])
{
    const float INF = 1e30f;
    float cur0 = 0.f;      // best total, incoming bond contribution = 0
    float cur1 = INF;      // best total, incoming = |zz_{i-1}|
    float zprev = 0.f;
#pragma unroll
    for (int i = 0; i < NQ - 1; i++) {
        const float xi = fabsf(px[i]);
        const float zi = fabsf(pzz[i]);
        // assign bond i LEFT (to site i): site cost sqrt(x^2+(r+zi)^2), out 0
        const float left0 = cur0 + sqrtf(xi * xi + zi * zi);
        const float left1 = cur1 + sqrtf(xi * xi + (zprev + zi) * (zprev + zi));
        // assign bond i RIGHT (to site i+1): site cost sqrt(x^2+r^2), out zi
        const float right0 = cur0 + xi;
        const float right1 = cur1 + sqrtf(xi * xi + zprev * zprev);
        cur0 = fminf(left0, left1);
        cur1 = fminf(right0, right1);
        zprev = zi;
    }
    const float xl = fabsf(px[NQ - 1]);
    return fminf(cur0 + xl, cur1 + sqrtf(xl * xl + zprev * zprev));
}

// ---------------------------------------------------------------------------
// One Chebyshev term on a CTA half (2048 entries, 4 per thread).
// Local s = (tid<<2)|cc (cc=0..3); global s adds rank<<11.
// Taps: bit0 = in-u64 swap (regs), bit1 = cross-u64 (regs),
// bits2..10 = 9 LDS.128 (partner float4 serves all 4 entries),
// bit11 = peer mirror LDS.128 (read AFTER tx-barrier wait).
// Warp-pipelined DSMEM exchange (16 x 512B bulks = expect_tx 8192).
// ---------------------------------------------------------------------------
template<bool EVEN>
__device__ __forceinline__ void cheb_term(
    u64 (&cur2)[2], u64 (&prevn2)[2], u64 (&psr2)[2], u64 (&psi2)[2],
    const u64 (&diag2)[2], const u64 (&pxp)[12],
    const ulonglong2* __restrict__ SRC, ulonglong2* __restrict__ DST,
    const ulonglong2* __restrict__ MIR,
    uint32_t bar_in, int& ph_in, bool do_wait,
    uint32_t bulk_dst_base, uint32_t bulk_src_base, uint32_t bulk_rbar,
    bool do_send, const int (&tapx)[9], int tid, float coef)
{
    u64 a0 = mul2_(diag2[0], cur2[0]);
    u64 a1 = mul2_(diag2[1], cur2[1]);
    a0 = fma2_(pxp[0], swap2(cur2[0]), a0);
    a1 = fma2_(pxp[0], swap2(cur2[1]), a1);
    a0 = fma2_(pxp[1], cur2[1], a0);
    a1 = fma2_(pxp[1], cur2[0], a1);
    // bits 2..10: own-half taps, one LDS.128 each
#pragma unroll
    for (int b = 0; b < 9; b++) {
        const ulonglong2 v = SRC[tapx[b]];
        a0 = fma2_(pxp[2 + b], v.x, a0);
        a1 = fma2_(pxp[2 + b], v.y, a1);
    }
    // wait for peer mirror (warp-pipelined send; usually complete), re-post expect
    if (do_wait) {
        mbar_wait(bar_in, (uint32_t)ph_in);
        ph_in ^= 1;
        if (tid == 0) mbar_expect(bar_in, 8192u);
    }
    // bit 11: peer mirror (ordered after the acquire wait above)
    {
        const ulonglong2 m = MIR[tid];
        a0 = fma2_(pxp[11], m.x, a0);
        a1 = fma2_(pxp[11], m.y, a1);
    }
    const u64 TWO2 = pk2(2.f, 2.f);
    const u64 M12  = pk2(-1.f, -1.f);
    const u64 C2   = pk2(coef, coef);
    const u64 nx0 = fma2_(TWO2, a0, prevn2[0]);   // 2*acc - prev
    const u64 nx1 = fma2_(TWO2, a1, prevn2[1]);
    DST[tid] = make_ulonglong2(nx0, nx1);
    // warp-pipelined exchange: send this warp's 512B chunk immediately
    if (do_send) {
        __syncwarp();
        if ((tid & 31) == 0) {
            asm volatile("fence.proxy.async.shared::cta;" ::: "memory");
            const uint32_t off = (uint32_t)(tid >> 5) * 512u;
            bulk_s2s(bulk_dst_base + off, bulk_src_base + off, 512u, bulk_rbar);
        }
    }
    prevn2[0] = mul2_(cur2[0], M12);
    prevn2[1] = mul2_(cur2[1], M12);
    cur2[0] = nx0;
    cur2[1] = nx1;
    if (EVEN) { psr2[0] = fma2_(C2, nx0, psr2[0]); psr2[1] = fma2_(C2, nx1, psr2[1]); }
    else      { psi2[0] = fma2_(C2, nx0, psi2[0]); psi2[1] = fma2_(C2, nx1, psi2[1]); }

    __syncthreads();   // all stores of this generation visible CTA-wide
}

// ---------------------------------------------------------------------------
// radix-2 gate on a complex pair (X basis p=0, Y basis p=1), no scaling
// ---------------------------------------------------------------------------
__device__ __forceinline__ void gate2(int p, float& r0, float& i0,
                                      float& r1, float& i1)
{
    const float a = r0, bb = i0, c = r1, d = i1;
    if (p == 0) { r0 = a + c; i0 = bb + d; r1 = a - c; i1 = bb - d; }
    else        { r0 = a + d; i0 = bb - c; r1 = a - d; i1 = bb + c; }
}

// ---------------------------------------------------------------------------
// Fused persistent kernel. 256 CTAs x 512 threads, cluster size 2.
//   bid 0..15 : evolve t=bid>>1, rank=bid&1 (2-CTA cluster per t);
//               afterwards measure (t, b=rank).
//   bid >= 16 : wait on flag[t]==2, then measure (t, b=2+...)
// ---------------------------------------------------------------------------
__global__ void __cluster_dims__(2, 1, 1) __launch_bounds__(512, 1)
fused_kernel(const int* __restrict__ d_init,
             const float* __restrict__ d_ts,
             const int* __restrict__ d_pauli,
             const int* __restrict__ d_idx,
             const float* __restrict__ d_px,
             const float* __restrict__ d_pzz,
             float* __restrict__ d_out)
{
    // pool (32KB): buf0|buf1|mir0|mir1 (8KB each); coeffs after.
    // measure reuses [0, DIM) = re, [DIM, 2*DIM) = im.
    __shared__ __align__(16) float pool[2 * DIM + 2 * (KMAX + 1)];
    __shared__ __align__(8) unsigned long long s_bar[2];
    __shared__ int s_misc[3 * NQ + 2];

    const int tid = threadIdx.x;
    const int bid = blockIdx.x;

    int t, b;
    if (bid < 2 * TT) { t = bid >> 1; b = bid & 1; }
    else { const int j = bid - 2 * TT; t = j / 30; b = 2 + j % 30; }

    if (bid < 2 * TT) {
        // ================= EVOLVE (t, rank) =================
        ulonglong2* pairs = reinterpret_cast<ulonglong2*>(pool);
        ulonglong2* buf0 = pairs;            // gen-even (512 float4)
        ulonglong2* buf1 = pairs + 512;      // gen-odd
        ulonglong2* mir0 = pairs + 1024;     // peer gen-even
        ulonglong2* mir1 = pairs + 1536;     // peer gen-odd
        float* s_cr = pool + 2 * DIM;
        float* s_ci = s_cr + (KMAX + 1);

        uint32_t rank;
        asm("mov.u32 %0, %%cluster_ctarank;" : "=r"(rank));
        const uint32_t peer = rank ^ 1u;

        float px[NQ];
#pragma unroll
        for (int i = 0; i < NQ; i++) px[i] = d_px[i];
        float pzz[NQ - 1];
#pragma unroll
        for (int i = 0; i < NQ - 1; i++) pzz[i] = d_pzz[i];

        // tight rigorous spectral bound (anticommuting-pair DP)
        float lambda = lambda_bound(px, pzz);
        if (lambda < 1e-20f) lambda = 1e-20f;
        const float inv_l = 1.0f / lambda;
#pragma unroll
        for (int i = 0; i < NQ; i++) px[i] *= inv_l;

        u64 pxp[12];
#pragma unroll
        for (int i = 0; i < NQ; i++) pxp[i] = pk2(px[i], px[i]);

        // scaled diagonal for owned entries: s = (rank<<11)|(tid<<2)|cc
        float diag[4];
#pragma unroll
        for (int cc = 0; cc < 4; cc++) {
            const int s = ((int)rank << 11) | (tid << 2) | cc;
            float d = 0.f;
#pragma unroll
            for (int i = 0; i < NQ - 1; i++) {
                const int bi = (s >> i) & 1;
                const int bj = (s >> (i + 1)) & 1;
                d += (bi == bj) ? pzz[i] : -pzz[i];
            }
            diag[cc] = d * inv_l;
        }
        u64 diag2[2] = { pk2(diag[0], diag[1]), pk2(diag[2], diag[3]) };

        // thread 0: Bessel coefficients + adaptive trim + barrier init
        if (tid == 0) {
            double x = (double)d_ts[t] * (double)lambda;
            if (x < 1e-5) x = 1e-5;
            int K = (int)ceil(x) + 16;
            if (K > KMAX) K = KMAX;
            if (K < 2)    K = 2;
            const int M = K + 14;
            double v[KMAX + 16];
            v[M] = 1e-30;
            const double inv_x = 1.0 / x;
            double up = 0.0;
            for (int k = M; k >= 1; k--) {
                const double nv = (2.0 * (double)k * inv_x) * v[k] - up;
                up = v[k];
                v[k - 1] = nv;
            }
            double S = v[0];
            for (int m = 2; m <= M; m += 2) S += 2.0 * v[m];
            const double invS = 1.0 / S;
            while (K > 2 && fabs(v[K] * invS) < 4e-4) K--;   // adaptive trim
            for (int k = 0; k <= K; k++) {
                const double Jk = v[k] * invS;
                const double c  = (k == 0) ? Jk : 2.0 * Jk;
                float cr = 0.f, ci = 0.f;
                switch (k & 3) {         // (-i)^k
                    case 0: cr = (float)c;  break;
                    case 1: ci = (float)-c; break;
                    case 2: cr = (float)-c; break;
                    case 3: ci = (float)c;  break;
                }
                s_cr[k] = cr;
                s_ci[k] = ci;
            }
            s_misc[0] = K;
            const uint32_t b0 = smem_u32(&s_bar[0]);
            const uint32_t b1 = smem_u32(&s_bar[1]);
            asm volatile("mbarrier.init.shared.b64 [%0], 1;" :: "r"(b0) : "memory");
            asm volatile("mbarrier.init.shared.b64 [%0], 1;" :: "r"(b1) : "memory");
            mbar_expect(b0, 8192u);      // phase 0, stage 0 (even gens)
            mbar_expect(b1, 8192u);      // phase 0, stage 1 (odd gens)
        }
        __syncthreads();

        const int K    = s_misc[0];
        const int init = *d_init;

        // tap pair-indices (tid xor bit) and remote addresses
        int tapx[9];
#pragma unroll
        for (int b2 = 0; b2 < 9; b2++) tapx[b2] = tid ^ (1 << b2);
        const uint32_t pbase = smem_u32(pool);
        const uint32_t bar0 = smem_u32(&s_bar[0]);
        const uint32_t bar1 = smem_u32(&s_bar[1]);
        const uint32_t pmir0 = mapa32(pbase + 16384u, peer);
        const uint32_t pmir1 = mapa32(pbase + 24576u, peer);
        const uint32_t pbar0 = mapa32(bar0, peer);
        const uint32_t pbar1 = mapa32(bar1, peer);

        // phi_0 = e_init ; phi_1 = H' e_init (analytic), own half + peer mirror
        u64 cur2[2], prevn2[2], psr2[2], psi2[2];
        const float cr0 = s_cr[0], ci1 = s_ci[1];
        {
            float p0v[4], p1v[4], q1v[4];
#pragma unroll
            for (int cc = 0; cc < 4; cc++) {
                const int so = ((int)rank << 11) | (tid << 2) | cc;
                const int sp = ((int)peer << 11) | (tid << 2) | cc;
                p0v[cc] = (so == init) ? 1.f : 0.f;
                float p1 = (so == init) ? diag[cc] : 0.f;
                int d = so ^ init;
#pragma unroll
                for (int i = 0; i < NQ; i++)
                    if (d == (1 << i)) p1 = px[i];
                p1v[cc] = p1;
                float q1 = 0.f;
                if (sp == init) {
                    float dd = 0.f;
#pragma unroll
                    for (int i = 0; i < NQ - 1; i++) {
                        const int bi = (sp >> i) & 1;
                        const int bj = (sp >> (i + 1)) & 1;
                        dd += (bi == bj) ? pzz[i] : -pzz[i];
                    }
                    q1 = dd * inv_l;
                }
                d = sp ^ init;
#pragma unroll
                for (int i = 0; i < NQ; i++)
                    if (d == (1 << i)) q1 = px[i];
                q1v[cc] = q1;
            }
            cur2[0]   = pk2(p1v[0], p1v[1]);
            cur2[1]   = pk2(p1v[2], p1v[3]);
            prevn2[0] = pk2(-p0v[0], -p0v[1]);
            prevn2[1] = pk2(-p0v[2], -p0v[3]);
            psr2[0]   = pk2(cr0 * p0v[0], cr0 * p0v[1]);
            psr2[1]   = pk2(cr0 * p0v[2], cr0 * p0v[3]);
            psi2[0]   = pk2(ci1 * p1v[0], ci1 * p1v[1]);
            psi2[1]   = pk2(ci1 * p1v[2], ci1 * p1v[3]);
            buf1[tid] = make_ulonglong2(cur2[0], cur2[1]);            // phi_1
            mir1[tid] = make_ulonglong2(pk2(q1v[0], q1v[1]),
                                        pk2(q1v[2], q1v[3]));         // peer phi_1
        }
        __syncthreads();
        asm volatile("barrier.cluster.arrive.aligned;" ::: "memory");
        asm volatile("barrier.cluster.wait.aligned;"   ::: "memory");

        int ph0 = 0, ph1 = 0;
        for (int k = 2; k <= K; k += 2) {
            // even k: consumes buf1/mir1 (gen k-1), produces buf0, sends buf0
            cheb_term<true>(cur2, prevn2, psr2, psi2, diag2, pxp,
                            buf1, buf0, mir1,
                            bar1, ph1, (k > 2),
                            pmir0, pbase, pbar0, (k < K),
                            tapx, tid, s_cr[k]);
            if (k + 1 <= K)
                cheb_term<false>(cur2, prevn2, psr2, psi2, diag2, pxp,
                                 buf0, buf1, mir0,
                                 bar0, ph0, true,
                                 pmir1, pbase + 8192u, pbar1, (k + 1 < K),
                                 tapx, tid, s_ci[k + 1]);
        }

        // publish my half + count flag
        {
            float pr0, pr1, pr2v, pr3, pi0, pi1, pi2v, pi3;
            upk2(psr2[0], pr0, pr1); upk2(psr2[1], pr2v, pr3);
            upk2(psi2[0], pi0, pi1); upk2(psi2[1], pi2v, pi3);
            const int s = ((int)rank << 11) | (tid << 2);
            g_states[t][s]     = make_float2(pr0, pi0);
            g_states[t][s | 1] = make_float2(pr1, pi1);
            g_states[t][s | 2] = make_float2(pr2v, pi2v);
            g_states[t][s | 3] = make_float2(pr3, pi3);
        }
        __syncthreads();
        if (tid == 0) {
            __threadfence();
            atomicAdd(&g_flag[t], 1);
        }
        // keep cluster alive until both ranks stop touching peer smem
        asm volatile("barrier.cluster.arrive.aligned;" ::: "memory");
        asm volatile("barrier.cluster.wait.aligned;"   ::: "memory");
    }

    // ================= WAIT for both halves of t =================
    if (tid == 0) {
        while (ld_acquire(&g_flag[t]) < 2) __nanosleep(64);
        const int n = atomicAdd(&g_cnt[t], 1);
        if (n == 31) {               // last of 32 consumers: self-clean
            g_cnt[t]  = 0;
            g_flag[t] = 0;
        }
    }
    __syncthreads();

    // ================= MEASURE (t, b) =================
    {
        float* re = pool;
        float* im = pool + DIM;
        int* p_raw = s_misc;
        int* nzm   = s_misc + NQ;
        int* nzp   = s_misc + 2 * NQ;
        int* s_nnz = s_misc + 3 * NQ;

        if (tid < NQ) p_raw[tid] = d_pauli[b * NQ + tid];

#pragma unroll
        for (int r = 0; r < DIM / 512; r++) {
            const int s = tid + (r << 9);
            const float2 v = __ldcg(&g_states[t][s]);
            re[s] = v.x;
            im[s] = v.y;
        }
        __syncthreads();

        if (tid == 0) {
            int c = 0;
            for (int m = NQ - 1; m >= 0; m--) {
                const int p = p_raw[NQ - 1 - m];
                if (p != 2) { nzm[c] = m; nzp[c] = p; c++; }
            }
            *s_nnz = c;
        }
        __syncthreads();

        const int nnz = *s_nnz;
        int i = 0;
        // radix-8: three non-Z qubits per sweep (mh > mm > ml; list descending)
        for (; i + 2 < nnz; i += 3) {
            const int mh = nzm[i], mm = nzm[i + 1], ml = nzm[i + 2];
            const int ph_ = nzp[i], pm_ = nzp[i + 1], pl_ = nzp[i + 2];
            const int lml = (1 << ml) - 1;
            const int lmm = (1 << mm) - 1;
            const int lmh = (1 << mh) - 1;
            const int ol = 1 << ml, om = 1 << mm, oh = 1 << mh;
            int x = ((tid & ~lml) << 1) | (tid & lml);
            x = ((x & ~lmm) << 1) | (x & lmm);
            const int s0 = ((x & ~lmh) << 1) | (x & lmh);
            int sidx[8];
#pragma unroll
            for (int j = 0; j < 8; j++)
                sidx[j] = s0 | ((j & 1) ? ol : 0) | ((j & 2) ? om : 0) | ((j & 4) ? oh : 0);
            float rr[8], ii[8];
#pragma unroll
            for (int j = 0; j < 8; j++) { rr[j] = re[sidx[j]]; ii[j] = im[sidx[j]]; }
#pragma unroll
            for (int j = 0; j < 8; j += 2)
                gate2(pl_, rr[j], ii[j], rr[j + 1], ii[j + 1]);
#pragma unroll
            for (int j = 0; j < 2; j++) {
                gate2(pm_, rr[j], ii[j], rr[j + 2], ii[j + 2]);
                gate2(pm_, rr[j + 4], ii[j + 4], rr[j + 6], ii[j + 6]);
            }
#pragma unroll
            for (int j = 0; j < 4; j++)
                gate2(ph_, rr[j], ii[j], rr[j + 4], ii[j + 4]);
            const float sc = 0.35355339059327376f;   // (1/sqrt2)^3
#pragma unroll
            for (int j = 0; j < 8; j++) {
                re[sidx[j]] = rr[j] * sc;
                im[sidx[j]] = ii[j] * sc;
            }
            __syncthreads();
        }
        // leftover: two non-Z qubits (radix-4)
        if (i + 1 < nnz) {
            const int mh = nzm[i], ml = nzm[i + 1];
            const int ph_ = nzp[i], pl_ = nzp[i + 1];
            const int lml = (1 << ml) - 1;
            const int lmh = (1 << mh) - 1;
            const int ol = 1 << ml, oh = 1 << mh;
#pragma unroll
            for (int r = 0; r < 2; r++) {
                const int g = tid + (r << 9);
                const int x = ((g & ~lml) << 1) | (g & lml);
                const int s00 = ((x & ~lmh) << 1) | (x & lmh);
                float rr[4], ii[4];
                const int sidx[4] = { s00, s00 | ol, s00 | oh, s00 | oh | ol };
#pragma unroll
                for (int j = 0; j < 4; j++) { rr[j] = re[sidx[j]]; ii[j] = im[sidx[j]]; }
                gate2(pl_, rr[0], ii[0], rr[1], ii[1]);
                gate2(pl_, rr[2], ii[2], rr[3], ii[3]);
                gate2(ph_, rr[0], ii[0], rr[2], ii[2]);
                gate2(ph_, rr[1], ii[1], rr[3], ii[3]);
#pragma unroll
                for (int j = 0; j < 4; j++) {
                    re[sidx[j]] = rr[j] * 0.5f;
                    im[sidx[j]] = ii[j] * 0.5f;
                }
            }
            i += 2;
            __syncthreads();
        }
        // leftover: single non-Z qubit (radix-2)
        if (i < nnz) {
            const int m = nzm[i], p = nzp[i];
            const int lm = (1 << m) - 1;
            const float s2 = 0.70710678118654752f;
#pragma unroll
            for (int r = 0; r < 4; r++) {
                const int q  = tid + (r << 9);
                const int sA = ((q & ~lm) << 1) | (q & lm);
                const int sB = sA | (1 << m);
                float r0 = re[sA], i0 = im[sA];
                float r1 = re[sB], i1 = im[sB];
                gate2(p, r0, i0, r1, i1);
                re[sA] = r0 * s2; im[sA] = i0 * s2;
                re[sB] = r1 * s2; im[sB] = i1 * s2;
            }
            __syncthreads();
        }

        if (tid < SHOTS) {
            const int base2 = (t * BB + b) * SHOTS;
            const int idx   = d_idx[base2 + tid];
            const float pr  = re[idx];
            const float pi  = im[idx];
            d_out[base2 + tid] = pr * pr + pi * pi;
        }
    }
}

// ---------------------------------------------------------------------------
extern "C" void kernel_launch(void* const* d_in, const int* in_sizes, int n_in,
                              void* d_out, int out_size)
{
    const int*   d_init  = (const int*)  d_in[0];
    const float* d_ts    = (const float*)d_in[1];
    const int*   d_pauli = (const int*)  d_in[2];
    const int*   d_idx   = (const int*)  d_in[3];
    const float* d_px    = (const float*)d_in[4];
    const float* d_pzz   = (const float*)d_in[5];

    fused_kernel<<<TT * BB, 512>>>(d_init, d_ts, d_pauli, d_idx,
                                   d_px, d_pzz, (float*)d_out);
}

// round 17
// speedup vs baseline: 1.5603x; 1.3092x over previous
#include <cuda_runtime.h>
#include <math.h>
#include <stdint.h>

#define NQ    12
#define TT    8
#define BB    32
#define SHOTS 256
#define KMAX  80
#define DIM   4096

typedef unsigned long long u64;

// Evolved states exp(-i t H)|init>, one complex vector per t, plus sync flags.
__device__ float2 g_states[TT][DIM];
__device__ int    g_flag[TT];   // counts ranks published (0..2); self-cleaning
__device__ int    g_cnt[TT];    // consumer count for self-clean

__device__ __forceinline__ int ld_acquire(const int* p) {
    int v;
    asm volatile("ld.acquire.gpu.s32 %0, [%1];" : "=r"(v) : "l"(p) : "memory");
    return v;
}
__device__ __forceinline__ uint32_t smem_u32(const void* p) {
    uint32_t a;
    asm("{ .reg .u64 t; cvta.to.shared.u64 t, %1; cvt.u32.u64 %0, t; }"
        : "=r"(a) : "l"(p));
    return a;
}
__device__ __forceinline__ uint32_t mapa32(uint32_t a, uint32_t r) {
    uint32_t d;
    asm("mapa.shared::cluster.u32 %0, %1, %2;" : "=r"(d) : "r"(a), "r"(r));
    return d;
}
__device__ __forceinline__ void mbar_wait(uint32_t bar, uint32_t parity) {
    asm volatile(
        "{\n\t.reg .pred P;\n\t"
        "WL_%=:\n\t"
        "mbarrier.try_wait.parity.acquire.cta.shared::cta.b64 P, [%0], %1, 0x989680;\n\t"
        "@P bra.uni WD_%=;\n\t"
        "bra.uni WL_%=;\n\t"
        "WD_%=:\n\t}"
        :: "r"(bar), "r"(parity) : "memory");
}
__device__ __forceinline__ void mbar_expect(uint32_t bar, uint32_t bytes) {
    asm volatile("mbarrier.arrive.expect_tx.shared.b64 _, [%0], %1;"
                 :: "r"(bar), "r"(bytes) : "memory");
}
__device__ __forceinline__ void bulk_s2s(uint32_t dst, uint32_t src,
                                         uint32_t bytes, uint32_t rbar) {
    asm volatile(
        "cp.async.bulk.shared::cluster.shared::cta.mbarrier::complete_tx::bytes "
        "[%0], [%1], %2, [%3];"
        :: "r"(dst), "r"(src), "r"(bytes), "r"(rbar) : "memory");
}

// ---- packed f32x2 helpers ----
__device__ __forceinline__ u64 pk2(float lo, float hi) {
    u64 r; asm("mov.b64 %0, {%1,%2};" : "=l"(r) : "f"(lo), "f"(hi)); return r;
}
__device__ __forceinline__ void upk2(u64 v, float& lo, float& hi) {
    asm("mov.b64 {%0,%1}, %2;" : "=f"(lo), "=f"(hi) : "l"(v));
}
__device__ __forceinline__ u64 swap2(u64 v) {
    float lo, hi; upk2(v, lo, hi); return pk2(hi, lo);
}
__device__ __forceinline__ u64 fma2_(u64 a, u64 b, u64 c) {
    u64 d; asm("fma.rn.f32x2 %0, %1, %2, %3;" : "=l"(d) : "l"(a), "l"(b), "l"(c));
    return d;
}
__device__ __forceinline__ u64 mul2_(u64 a, u64 b) {
    u64 d; asm("mul.rn.f32x2 %0, %1, %2;" : "=l"(d) : "l"(a), "l"(b)); return d;
}

// ---------------------------------------------------------------------------
// Rigorous spectral bound, tighter than the 1-norm (anticommuting-pair DP).
// ---------------------------------------------------------------------------
__device__ __forceinline__ float lambda_bound(const float (&px)[NQ],
                                              const float (&pzz)[NQ - 1])
{
    const float INF = 1e30f;
    float cur0 = 0.f;
    float cur1 = INF;
    float zprev = 0.f;
#pragma unroll
    for (int i = 0; i < NQ - 1; i++) {
        const float xi = fabsf(px[i]);
        const float zi = fabsf(pzz[i]);
        const float left0 = cur0 + sqrtf(xi * xi + zi * zi);
        const float left1 = cur1 + sqrtf(xi * xi + (zprev + zi) * (zprev + zi));
        const float right0 = cur0 + xi;
        const float right1 = cur1 + sqrtf(xi * xi + zprev * zprev);
        cur0 = fminf(left0, left1);
        cur1 = fminf(right0, right1);
        zprev = zi;
    }
    const float xl = fabsf(px[NQ - 1]);
    return fminf(cur0 + xl, cur1 + sqrtf(xl * xl + zprev * zprev));
}

// ---------------------------------------------------------------------------
// One Chebyshev term on a CTA half (2048 entries, 4 per thread).
// Local s = (tid<<2)|cc; global s adds rank<<11. Taps: bit0/bit1 regs,
// bits2..10 = 9 LDS.128, bit11 = peer mirror (after tx-barrier wait).
// Warp-pipelined DSMEM exchange (16 x 512B bulks = expect_tx 8192).
// ---------------------------------------------------------------------------
template<bool EVEN>
__device__ __forceinline__ void cheb_term(
    u64 (&cur2)[2], u64 (&prevn2)[2], u64 (&psr2)[2], u64 (&psi2)[2],
    const u64 (&diag2)[2], const u64 (&pxp)[12],
    const ulonglong2* __restrict__ SRC, ulonglong2* __restrict__ DST,
    const ulonglong2* __restrict__ MIR,
    uint32_t bar_in, int& ph_in, bool do_wait,
    uint32_t bulk_dst_base, uint32_t bulk_src_base, uint32_t bulk_rbar,
    bool do_send, const int (&tapx)[9], int tid, float coef)
{
    u64 a0 = mul2_(diag2[0], cur2[0]);
    u64 a1 = mul2_(diag2[1], cur2[1]);
    a0 = fma2_(pxp[0], swap2(cur2[0]), a0);
    a1 = fma2_(pxp[0], swap2(cur2[1]), a1);
    a0 = fma2_(pxp[1], cur2[1], a0);
    a1 = fma2_(pxp[1], cur2[0], a1);
#pragma unroll
    for (int b = 0; b < 9; b++) {
        const ulonglong2 v = SRC[tapx[b]];
        a0 = fma2_(pxp[2 + b], v.x, a0);
        a1 = fma2_(pxp[2 + b], v.y, a1);
    }
    if (do_wait) {
        mbar_wait(bar_in, (uint32_t)ph_in);
        ph_in ^= 1;
        if (tid == 0) mbar_expect(bar_in, 8192u);
    }
    {
        const ulonglong2 m = MIR[tid];
        a0 = fma2_(pxp[11], m.x, a0);
        a1 = fma2_(pxp[11], m.y, a1);
    }
    const u64 TWO2 = pk2(2.f, 2.f);
    const u64 M12  = pk2(-1.f, -1.f);
    const u64 C2   = pk2(coef, coef);
    const u64 nx0 = fma2_(TWO2, a0, prevn2[0]);
    const u64 nx1 = fma2_(TWO2, a1, prevn2[1]);
    DST[tid] = make_ulonglong2(nx0, nx1);
    if (do_send) {
        __syncwarp();
        if ((tid & 31) == 0) {
            asm volatile("fence.proxy.async.shared::cta;" ::: "memory");
            const uint32_t off = (uint32_t)(tid >> 5) * 512u;
            bulk_s2s(bulk_dst_base + off, bulk_src_base + off, 512u, bulk_rbar);
        }
    }
    prevn2[0] = mul2_(cur2[0], M12);
    prevn2[1] = mul2_(cur2[1], M12);
    cur2[0] = nx0;
    cur2[1] = nx1;
    if (EVEN) { psr2[0] = fma2_(C2, nx0, psr2[0]); psr2[1] = fma2_(C2, nx1, psr2[1]); }
    else      { psi2[0] = fma2_(C2, nx0, psi2[0]); psi2[1] = fma2_(C2, nx1, psi2[1]); }

    __syncthreads();
}

// ---------------------------------------------------------------------------
__device__ __forceinline__ void gate2(int p, float& r0, float& i0,
                                      float& r1, float& i1)
{
    const float a = r0, bb = i0, c = r1, d = i1;
    if (p == 0) { r0 = a + c; i0 = bb + d; r1 = a - c; i1 = bb - d; }
    else        { r0 = a + d; i0 = bb - c; r1 = a - d; i1 = bb + c; }
}

// ---------------------------------------------------------------------------
// Fused persistent kernel. 256 CTAs x 512 threads, cluster size 2.
// ---------------------------------------------------------------------------
__global__ void __cluster_dims__(2, 1, 1) __launch_bounds__(512, 1)
fused_kernel(const int* __restrict__ d_init,
             const float* __restrict__ d_ts,
             const int* __restrict__ d_pauli,
             const int* __restrict__ d_idx,
             const float* __restrict__ d_px,
             const float* __restrict__ d_pzz,
             float* __restrict__ d_out)
{
    __shared__ __align__(16) float pool[2 * DIM + 2 * (KMAX + 1)];
    __shared__ __align__(8) unsigned long long s_bar[2];
    __shared__ int s_misc[3 * NQ + 2];

    const int tid = threadIdx.x;
    const int bid = blockIdx.x;

    int t, b;
    if (bid < 2 * TT) { t = bid >> 1; b = bid & 1; }
    else { const int j = bid - 2 * TT; t = j / 30; b = 2 + j % 30; }

    if (bid < 2 * TT) {
        // ================= EVOLVE (t, rank) =================
        ulonglong2* pairs = reinterpret_cast<ulonglong2*>(pool);
        ulonglong2* buf0 = pairs;
        ulonglong2* buf1 = pairs + 512;
        ulonglong2* mir0 = pairs + 1024;
        ulonglong2* mir1 = pairs + 1536;
        float* s_cr = pool + 2 * DIM;
        float* s_ci = s_cr + (KMAX + 1);

        uint32_t rank;
        asm("mov.u32 %0, %%cluster_ctarank;" : "=r"(rank));
        const uint32_t peer = rank ^ 1u;

        float px[NQ];
#pragma unroll
        for (int i = 0; i < NQ; i++) px[i] = d_px[i];
        float pzz[NQ - 1];
#pragma unroll
        for (int i = 0; i < NQ - 1; i++) pzz[i] = d_pzz[i];

        float lambda = lambda_bound(px, pzz);
        if (lambda < 1e-20f) lambda = 1e-20f;
        const float inv_l = 1.0f / lambda;
#pragma unroll
        for (int i = 0; i < NQ; i++) px[i] *= inv_l;

        u64 pxp[12];
#pragma unroll
        for (int i = 0; i < NQ; i++) pxp[i] = pk2(px[i], px[i]);

        float diag[4];
#pragma unroll
        for (int cc = 0; cc < 4; cc++) {
            const int s = ((int)rank << 11) | (tid << 2) | cc;
            float d = 0.f;
#pragma unroll
            for (int i = 0; i < NQ - 1; i++) {
                const int bi = (s >> i) & 1;
                const int bj = (s >> (i + 1)) & 1;
                d += (bi == bj) ? pzz[i] : -pzz[i];
            }
            diag[cc] = d * inv_l;
        }
        u64 diag2[2] = { pk2(diag[0], diag[1]), pk2(diag[2], diag[3]) };

        // thread 0: Bessel coefficients. Float Miller for x >= 2 (fast path,
        // FFMA lat 4 vs DFMA ~47; downward recurrence is stable, seed 1e-12f
        // leaves >= 1e3 headroom at growth <= ~1e35). Double path for x < 2.
        if (tid == 0) {
            double xd = (double)d_ts[t] * (double)lambda;
            if (xd < 1e-5) xd = 1e-5;
            int K = (int)ceil(xd) + 16;
            if (K > KMAX) K = KMAX;
            if (K < 2)    K = 2;
            const int M = K + 14;

            if (xd >= 2.0) {
                const float x = (float)xd;
                float v[KMAX + 16];
                v[M] = 1e-12f;
                const float inv_x = 1.0f / x;
                float up = 0.0f;
                for (int k = M; k >= 1; k--) {
                    const float nv = fmaf(2.0f * (float)k * inv_x, v[k], -up);
                    up = v[k];
                    v[k - 1] = nv;
                }
                float S = v[0];
                for (int m = 2; m <= M; m += 2) S += 2.0f * v[m];
                const float invS = 1.0f / S;
                while (K > 2 && fabsf(v[K] * invS) < 1e-3f) K--;   // trim
                for (int k = 0; k <= K; k++) {
                    const float Jk = v[k] * invS;
                    const float c  = (k == 0) ? Jk : 2.0f * Jk;
                    float cr = 0.f, ci = 0.f;
                    switch (k & 3) {     // (-i)^k
                        case 0: cr = c;  break;
                        case 1: ci = -c; break;
                        case 2: cr = -c; break;
                        case 3: ci = c;  break;
                    }
                    s_cr[k] = cr;
                    s_ci[k] = ci;
                }
            } else {
                double v[KMAX + 16];
                v[M] = 1e-30;
                const double inv_x = 1.0 / xd;
                double up = 0.0;
                for (int k = M; k >= 1; k--) {
                    const double nv = (2.0 * (double)k * inv_x) * v[k] - up;
                    up = v[k];
                    v[k - 1] = nv;
                }
                double S = v[0];
                for (int m = 2; m <= M; m += 2) S += 2.0 * v[m];
                const double invS = 1.0 / S;
                while (K > 2 && fabs(v[K] * invS) < 1e-3) K--;     // trim
                for (int k = 0; k <= K; k++) {
                    const double Jk = v[k] * invS;
                    const double c  = (k == 0) ? Jk : 2.0 * Jk;
                    float cr = 0.f, ci = 0.f;
                    switch (k & 3) {     // (-i)^k
                        case 0: cr = (float)c;  break;
                        case 1: ci = (float)-c; break;
                        case 2: cr = (float)-c; break;
                        case 3: ci = (float)c;  break;
                    }
                    s_cr[k] = cr;
                    s_ci[k] = ci;
                }
            }
            s_misc[0] = K;
            const uint32_t b0 = smem_u32(&s_bar[0]);
            const uint32_t b1 = smem_u32(&s_bar[1]);
            asm volatile("mbarrier.init.shared.b64 [%0], 1;" :: "r"(b0) : "memory");
            asm volatile("mbarrier.init.shared.b64 [%0], 1;" :: "r"(b1) : "memory");
            mbar_expect(b0, 8192u);
            mbar_expect(b1, 8192u);
        }
        __syncthreads();

        const int K    = s_misc[0];
        const int init = *d_init;

        int tapx[9];
#pragma unroll
        for (int b2 = 0; b2 < 9; b2++) tapx[b2] = tid ^ (1 << b2);
        const uint32_t pbase = smem_u32(pool);
        const uint32_t bar0 = smem_u32(&s_bar[0]);
        const uint32_t bar1 = smem_u32(&s_bar[1]);
        const uint32_t pmir0 = mapa32(pbase + 16384u, peer);
        const uint32_t pmir1 = mapa32(pbase + 24576u, peer);
        const uint32_t pbar0 = mapa32(bar0, peer);
        const uint32_t pbar1 = mapa32(bar1, peer);

        // phi_0 = e_init ; phi_1 = H' e_init (analytic), own half + peer mirror
        u64 cur2[2], prevn2[2], psr2[2], psi2[2];
        const float cr0 = s_cr[0], ci1 = s_ci[1];
        {
            float p0v[4], p1v[4], q1v[4];
#pragma unroll
            for (int cc = 0; cc < 4; cc++) {
                const int so = ((int)rank << 11) | (tid << 2) | cc;
                const int sp = ((int)peer << 11) | (tid << 2) | cc;
                p0v[cc] = (so == init) ? 1.f : 0.f;
                float p1 = (so == init) ? diag[cc] : 0.f;
                int d = so ^ init;
#pragma unroll
                for (int i = 0; i < NQ; i++)
                    if (d == (1 << i)) p1 = px[i];
                p1v[cc] = p1;
                float q1 = 0.f;
                if (sp == init) {
                    float dd = 0.f;
#pragma unroll
                    for (int i = 0; i < NQ - 1; i++) {
                        const int bi = (sp >> i) & 1;
                        const int bj = (sp >> (i + 1)) & 1;
                        dd += (bi == bj) ? pzz[i] : -pzz[i];
                    }
                    q1 = dd * inv_l;
                }
                d = sp ^ init;
#pragma unroll
                for (int i = 0; i < NQ; i++)
                    if (d == (1 << i)) q1 = px[i];
                q1v[cc] = q1;
            }
            cur2[0]   = pk2(p1v[0], p1v[1]);
            cur2[1]   = pk2(p1v[2], p1v[3]);
            prevn2[0] = pk2(-p0v[0], -p0v[1]);
            prevn2[1] = pk2(-p0v[2], -p0v[3]);
            psr2[0]   = pk2(cr0 * p0v[0], cr0 * p0v[1]);
            psr2[1]   = pk2(cr0 * p0v[2], cr0 * p0v[3]);
            psi2[0]   = pk2(ci1 * p1v[0], ci1 * p1v[1]);
            psi2[1]   = pk2(ci1 * p1v[2], ci1 * p1v[3]);
            buf1[tid] = make_ulonglong2(cur2[0], cur2[1]);
            mir1[tid] = make_ulonglong2(pk2(q1v[0], q1v[1]),
                                        pk2(q1v[2], q1v[3]));
        }
        __syncthreads();
        asm volatile("barrier.cluster.arrive.aligned;" ::: "memory");
        asm volatile("barrier.cluster.wait.aligned;"   ::: "memory");

        int ph0 = 0, ph1 = 0;
        for (int k = 2; k <= K; k += 2) {
            cheb_term<true>(cur2, prevn2, psr2, psi2, diag2, pxp,
                            buf1, buf0, mir1,
                            bar1, ph1, (k > 2),
                            pmir0, pbase, pbar0, (k < K),
                            tapx, tid, s_cr[k]);
            if (k + 1 <= K)
                cheb_term<false>(cur2, prevn2, psr2, psi2, diag2, pxp,
                                 buf0, buf1, mir0,
                                 bar0, ph0, true,
                                 pmir1, pbase + 8192u, pbar1, (k + 1 < K),
                                 tapx, tid, s_ci[k + 1]);
        }

        // publish my half + count flag
        {
            float pr0, pr1, pr2v, pr3, pi0, pi1, pi2v, pi3;
            upk2(psr2[0], pr0, pr1); upk2(psr2[1], pr2v, pr3);
            upk2(psi2[0], pi0, pi1); upk2(psi2[1], pi2v, pi3);
            const int s = ((int)rank << 11) | (tid << 2);
            g_states[t][s]     = make_float2(pr0, pi0);
            g_states[t][s | 1] = make_float2(pr1, pi1);
            g_states[t][s | 2] = make_float2(pr2v, pi2v);
            g_states[t][s | 3] = make_float2(pr3, pi3);
        }
        __syncthreads();
        if (tid == 0) {
            __threadfence();
            atomicAdd(&g_flag[t], 1);
        }
        asm volatile("barrier.cluster.arrive.aligned;" ::: "memory");
        asm volatile("barrier.cluster.wait.aligned;"   ::: "memory");
    }

    // ================= WAIT for both halves of t =================
    if (tid == 0) {
        while (ld_acquire(&g_flag[t]) < 2) __nanosleep(64);
        const int n = atomicAdd(&g_cnt[t], 1);
        if (n == 31) {
            g_cnt[t]  = 0;
            g_flag[t] = 0;
        }
    }
    __syncthreads();

    // ================= MEASURE (t, b) =================
    {
        float* re = pool;
        float* im = pool + DIM;
        int* p_raw = s_misc;
        int* nzm   = s_misc + NQ;
        int* nzp   = s_misc + 2 * NQ;
        int* s_nnz = s_misc + 3 * NQ;

        if (tid < NQ) p_raw[tid] = d_pauli[b * NQ + tid];

#pragma unroll
        for (int r = 0; r < DIM / 512; r++) {
            const int s = tid + (r << 9);
            const float2 v = __ldcg(&g_states[t][s]);
            re[s] = v.x;
            im[s] = v.y;
        }
        __syncthreads();

        if (tid == 0) {
            int c = 0;
            for (int m = NQ - 1; m >= 0; m--) {
                const int p = p_raw[NQ - 1 - m];
                if (p != 2) { nzm[c] = m; nzp[c] = p; c++; }
            }
            *s_nnz = c;
        }
        __syncthreads();

        const int nnz = *s_nnz;
        int i = 0;
        for (; i + 2 < nnz; i += 3) {
            const int mh = nzm[i], mm = nzm[i + 1], ml = nzm[i + 2];
            const int ph_ = nzp[i], pm_ = nzp[i + 1], pl_ = nzp[i + 2];
            const int lml = (1 << ml) - 1;
            const int lmm = (1 << mm) - 1;
            const int lmh = (1 << mh) - 1;
            const int ol = 1 << ml, om = 1 << mm, oh = 1 << mh;
            int x = ((tid & ~lml) << 1) | (tid & lml);
            x = ((x & ~lmm) << 1) | (x & lmm);
            const int s0 = ((x & ~lmh) << 1) | (x & lmh);
            int sidx[8];
#pragma unroll
            for (int j = 0; j < 8; j++)
                sidx[j] = s0 | ((j & 1) ? ol : 0) | ((j & 2) ? om : 0) | ((j & 4) ? oh : 0);
            float rr[8], ii[8];
#pragma unroll
            for (int j = 0; j < 8; j++) { rr[j] = re[sidx[j]]; ii[j] = im[sidx[j]]; }
#pragma unroll
            for (int j = 0; j < 8; j += 2)
                gate2(pl_, rr[j], ii[j], rr[j + 1], ii[j + 1]);
#pragma unroll
            for (int j = 0; j < 2; j++) {
                gate2(pm_, rr[j], ii[j], rr[j + 2], ii[j + 2]);
                gate2(pm_, rr[j + 4], ii[j + 4], rr[j + 6], ii[j + 6]);
            }
#pragma unroll
            for (int j = 0; j < 4; j++)
                gate2(ph_, rr[j], ii[j], rr[j + 4], ii[j + 4]);
            const float sc = 0.35355339059327376f;
#pragma unroll
            for (int j = 0; j < 8; j++) {
                re[sidx[j]] = rr[j] * sc;
                im[sidx[j]] = ii[j] * sc;
            }
            __syncthreads();
        }
        if (i + 1 < nnz) {
            const int mh = nzm[i], ml = nzm[i + 1];
            const int ph_ = nzp[i], pl_ = nzp[i + 1];
            const int lml = (1 << ml) - 1;
            const int lmh = (1 << mh) - 1;
            const int ol = 1 << ml, oh = 1 << mh;
#pragma unroll
            for (int r = 0; r < 2; r++) {
                const int g = tid + (r << 9);
                const int x = ((g & ~lml) << 1) | (g & lml);
                const int s00 = ((x & ~lmh) << 1) | (x & lmh);
                float rr[4], ii[4];
                const int sidx[4] = { s00, s00 | ol, s00 | oh, s00 | oh | ol };
#pragma unroll
                for (int j = 0; j < 4; j++) { rr[j] = re[sidx[j]]; ii[j] = im[sidx[j]]; }
                gate2(pl_, rr[0], ii[0], rr[1], ii[1]);
                gate2(pl_, rr[2], ii[2], rr[3], ii[3]);
                gate2(ph_, rr[0], ii[0], rr[2], ii[2]);
                gate2(ph_, rr[1], ii[1], rr[3], ii[3]);
#pragma unroll
                for (int j = 0; j < 4; j++) {
                    re[sidx[j]] = rr[j] * 0.5f;
                    im[sidx[j]] = ii[j] * 0.5f;
                }
            }
            i += 2;
            __syncthreads();
        }
        if (i < nnz) {
            const int m = nzm[i], p = nzp[i];
            const int lm = (1 << m) - 1;
            const float s2 = 0.70710678118654752f;
#pragma unroll
            for (int r = 0; r < 4; r++) {
                const int q  = tid + (r << 9);
                const int sA = ((q & ~lm) << 1) | (q & lm);
                const int sB = sA | (1 << m);
                float r0 = re[sA], i0 = im[sA];
                float r1 = re[sB], i1 = im[sB];
                gate2(p, r0, i0, r1, i1);
                re[sA] = r0 * s2; im[sA] = i0 * s2;
                re[sB] = r1 * s2; im[sB] = i1 * s2;
            }
            __syncthreads();
        }

        if (tid < SHOTS) {
            const int base2 = (t * BB + b) * SHOTS;
            const int idx   = d_idx[base2 + tid];
            const float pr  = re[idx];
            const float pi  = im[idx];
            d_out[base2 + tid] = pr * pr + pi * pi;
        }
    }
}

// ---------------------------------------------------------------------------
extern "C" void kernel_launch(void* const* d_in, const int* in_sizes, int n_in,
                              void* d_out, int out_size)
{
    const int*   d_init  = (const int*)  d_in[0];
    const float* d_ts    = (const float*)d_in[1];
    const int*   d_pauli = (const int*)  d_in[2];
    const int*   d_idx   = (const int*)  d_in[3];
    const float* d_px    = (const float*)d_in[4];
    const float* d_pzz   = (const float*)d_in[5];

    fused_kernel<<<TT * BB, 512>>>(d_init, d_ts, d_pauli, d_idx,
                                   d_px, d_pzz, (float*)d_out);
}